// round 6
// baseline (speedup 1.0000x reference)
#include <cuda_runtime.h>

// FPS (farthest point sampling), torch_geometric semantics (start at local idx 0).
// 16 clouds x 16384 points -> 4096 samples per cloud. One CTA per cloud.
// Rounding: no FMA contraction, d = (dx*dx + dy*dy) + dz*dz, subtraction exact
// via FADD of negated coordinate. argmax = first occurrence of max.
// OUTPUT: float32 VALUES of the global indices (harness compares as float).

#define N_CLOUDS 16
#define PTS      16384
#define M_SAMP   4096
#define THREADS  512
#define PAIRS    16      // 32 points per thread = 16 f32x2 pairs

__device__ __forceinline__ unsigned long long pack2(float lo, float hi) {
    unsigned long long r;
    asm("mov.b64 %0, {%1, %2};" : "=l"(r) : "f"(lo), "f"(hi));
    return r;
}
__device__ __forceinline__ void unpack2(unsigned long long v, float& lo, float& hi) {
    asm("mov.b64 {%0, %1}, %2;" : "=f"(lo), "=f"(hi) : "l"(v));
}
// Packed IEEE RN f32x2 ops (sm_100+): bit-identical to scalar FADD/FMUL.
__device__ __forceinline__ unsigned long long add2(unsigned long long a, unsigned long long b) {
    unsigned long long r;
    asm("add.rn.f32x2 %0, %1, %2;" : "=l"(r) : "l"(a), "l"(b));
    return r;
}
__device__ __forceinline__ unsigned long long mul2(unsigned long long a, unsigned long long b) {
    unsigned long long r;
    asm("mul.rn.f32x2 %0, %1, %2;" : "=l"(r) : "l"(a), "l"(b));
    return r;
}

extern __shared__ unsigned char smem_raw[];

__global__ __launch_bounds__(THREADS, 1)
void fps_kernel(const float* __restrict__ pos, float* __restrict__ out)
{
    // shared layout: [16 x u64 warp keys][4 x f32 selected point][16384 x f32 min-dist]
    unsigned long long* skeys = (unsigned long long*)smem_raw;
    float* ssel  = (float*)(smem_raw + 16 * 8);
    float* sdist = (float*)(smem_raw + 16 * 8 + 16);

    const int t = threadIdx.x;
    const int b = blockIdx.x;
    const float* p = pos + (size_t)b * PTS * 3;

    // Coordinates of this thread's 32 points, packed as f32x2 pairs.
    // Point j (0..31) of thread t has cloud-local index  g = t + (j << 9).
    unsigned long long CX[PAIRS], CY[PAIRS], CZ[PAIRS];
    const float INF = __int_as_float(0x7f800000);

    float* sdist_t = sdist + t;

#pragma unroll
    for (int pr = 0; pr < PAIRS; ++pr) {
        int g0 = t + ((2 * pr)     << 9);
        int g1 = t + ((2 * pr + 1) << 9);
        float x0 = p[3 * g0 + 0], y0 = p[3 * g0 + 1], z0 = p[3 * g0 + 2];
        float x1 = p[3 * g1 + 0], y1 = p[3 * g1 + 1], z1 = p[3 * g1 + 2];
        CX[pr] = pack2(x0, x1);
        CY[pr] = pack2(y0, y1);
        CZ[pr] = pack2(z0, z1);
        sdist_t[(2 * pr)     << 9] = INF;
        sdist_t[(2 * pr + 1) << 9] = INF;
    }
    if (t == 0) {
        // First pick is local index 0; its coords seed the first update.
        ssel[0] = p[0]; ssel[1] = p[1]; ssel[2] = p[2];
        out[b * M_SAMP] = (float)(b * PTS);
    }
    __syncthreads();

    const int lane = t & 31;
    const int wid  = t >> 5;

    for (int i = 1; i < M_SAMP; ++i) {
        const float sx = ssel[0], sy = ssel[1], sz = ssel[2];
        const unsigned long long nx2 = pack2(-sx, -sx);
        const unsigned long long ny2 = pack2(-sy, -sy);
        const unsigned long long nz2 = pack2(-sz, -sz);

        float best = 0.0f;   // dists >= 0; 0-claim is always valid
        int jj = 0;

#pragma unroll
        for (int pr = 0; pr < PAIRS; ++pr) {
            // p - s computed as p + (-s): exact (negation is exact).
            unsigned long long dx = add2(CX[pr], nx2);
            unsigned long long dy = add2(CY[pr], ny2);
            unsigned long long dz = add2(CZ[pr], nz2);
            // (dx^2 + dy^2) + dz^2, all RN, no contraction.
            unsigned long long s  = add2(add2(mul2(dx, dx), mul2(dy, dy)), mul2(dz, dz));
            float lo, hi;
            unpack2(s, lo, hi);
            {
                float old = sdist_t[(2 * pr) << 9];
                float nd  = fminf(old, lo);
                if (nd < old) sdist_t[(2 * pr) << 9] = nd;
                if (nd > best) { best = nd; jj = 2 * pr; }
            }
            {
                float old = sdist_t[(2 * pr + 1) << 9];
                float nd  = fminf(old, hi);
                if (nd < old) sdist_t[(2 * pr + 1) << 9] = nd;
                if (nd > best) { best = nd; jj = 2 * pr + 1; }
            }
        }

        // 64-bit key: high = float bits of dist (>=0, order-preserving),
        // low = ~idx so equal dists break toward the LOWEST index (jnp.argmax).
        unsigned int gidx = (unsigned int)t + ((unsigned int)jj << 9);
        unsigned long long key =
            ((unsigned long long)__float_as_uint(best) << 32) |
            (unsigned long long)(0xFFFFFFFFu - gidx);

#pragma unroll
        for (int off = 16; off > 0; off >>= 1) {
            unsigned long long o = __shfl_xor_sync(0xFFFFFFFFu, key, off);
            if (o > key) key = o;
        }
        if (lane == 0) skeys[wid] = key;
        __syncthreads();

        // Redundant final reduce by all threads (saves one barrier).
        unsigned long long k = skeys[0];
#pragma unroll
        for (int w = 1; w < 16; ++w) {
            unsigned long long o = skeys[w];
            if (o > k) k = o;
        }
        const unsigned int gw = 0xFFFFFFFFu - (unsigned int)k;

        // Owner thread publishes the winner's coords (compile-time indexed
        // predicated extraction; no dynamic register-array indexing).
        if ((int)(gw & 511u) == t) {
            const int jw  = (int)(gw >> 9);
            const int prw = jw >> 1;
            const int hw  = jw & 1;
            float wx = 0.f, wy = 0.f, wz = 0.f;
#pragma unroll
            for (int pr = 0; pr < PAIRS; ++pr) {
                if (pr == prw) {
                    float l0, h0, l1, h1, l2, h2;
                    unpack2(CX[pr], l0, h0);
                    unpack2(CY[pr], l1, h1);
                    unpack2(CZ[pr], l2, h2);
                    wx = hw ? h0 : l0;
                    wy = hw ? h1 : l1;
                    wz = hw ? h2 : l2;
                }
            }
            ssel[0] = wx; ssel[1] = wy; ssel[2] = wz;
        }
        // Index value as float32 (exact: indices < 2^24).
        if (t == 0) out[b * M_SAMP + i] = (float)(b * PTS + (int)gw);
        __syncthreads();
    }
}

extern "C" void kernel_launch(void* const* d_in, const int* in_sizes, int n_in,
                              void* d_out, int out_size)
{
    // Resolve inputs BY SIZE, not by position:
    //   pos   : 16*16384*3 = 786432 float32
    //   feats : 16*16384*128 = 2097152 float32
    //   batch : 16*16384 = 262144 ints
    const float* pos = nullptr;
    for (int i = 0; i < n_in; ++i) {
        if (in_sizes[i] == N_CLOUDS * PTS * 3) { pos = (const float*)d_in[i]; break; }
    }
    if (!pos) pos = (const float*)d_in[0];      // fallback: documented order

    float* out = (float*)d_out;                 // [N_CLOUDS*M_SAMP] float32 index values

    const size_t smem = 16 * 8 + 16 + (size_t)PTS * sizeof(float);
    cudaFuncSetAttribute(fps_kernel, cudaFuncAttributeMaxDynamicSharedMemorySize, (int)smem);
    fps_kernel<<<N_CLOUDS, THREADS, smem>>>(pos, out);
}

// round 8
// speedup vs baseline: 1.2189x; 1.2189x over previous
#include <cuda_runtime.h>
#include <cooperative_groups.h>

namespace cg = cooperative_groups;

// FPS, torch_geometric semantics. 16 clouds x 16384 -> 4096 samples/cloud.
// 2-CTA cluster per cloud (32 CTAs total), 8192 points per CTA, min-dists in
// REGISTERS (no smem dist array). Bit-exact arithmetic validated in R6:
//   d = (dx*dx + dy*dy) + dz*dz, RN, no FMA contraction, sub = add of negated.
// argmax = first occurrence of max (lowest cloud-local index) via u64 key.
// Output: float32 values of global indices.

#define N_CLOUDS 16
#define PTS      16384
#define M_SAMP   4096
#define THREADS  512
#define HALF     8192    // points per CTA
#define PAIRS    8       // 16 points per thread = 8 f32x2 pairs

__device__ __forceinline__ unsigned long long pack2(float lo, float hi) {
    unsigned long long r;
    asm("mov.b64 %0, {%1, %2};" : "=l"(r) : "f"(lo), "f"(hi));
    return r;
}
__device__ __forceinline__ void unpack2(unsigned long long v, float& lo, float& hi) {
    asm("mov.b64 {%0, %1}, %2;" : "=f"(lo), "=f"(hi) : "l"(v));
}
// Packed IEEE RN f32x2 ops (sm_100+): bit-identical to scalar FADD/FMUL.
__device__ __forceinline__ unsigned long long add2(unsigned long long a, unsigned long long b) {
    unsigned long long r;
    asm("add.rn.f32x2 %0, %1, %2;" : "=l"(r) : "l"(a), "l"(b));
    return r;
}
__device__ __forceinline__ unsigned long long mul2(unsigned long long a, unsigned long long b) {
    unsigned long long r;
    asm("mul.rn.f32x2 %0, %1, %2;" : "=l"(r) : "l"(a), "l"(b));
    return r;
}

__global__ __launch_bounds__(THREADS, 1) __cluster_dims__(2, 1, 1)
void fps_kernel(const float* __restrict__ pos, float* __restrict__ out)
{
    __shared__ unsigned long long skeys[16];      // per-warp reduced keys
    __shared__ unsigned long long ekey[2][2];     // [parity][rank] exchange keys
    __shared__ float ecoord[2][2][3];             // [parity][rank][xyz]

    cg::cluster_group cluster = cg::this_cluster();
    const unsigned rank = cluster.block_rank();   // 0 or 1 within the cloud
    const int b = blockIdx.x >> 1;                // cloud id
    const int base = (int)rank * HALF;            // cloud-local offset of this CTA's half

    const int t    = threadIdx.x;
    const int lane = t & 31;
    const int wid  = t >> 5;
    const float* p = pos + (size_t)b * PTS * 3;

    // This thread's 16 points: cloud-local index g = base + t + (k<<9), k=0..15.
    unsigned long long CX[PAIRS], CY[PAIRS], CZ[PAIRS];
    float d[2 * PAIRS];
    const float INF = __int_as_float(0x7f800000);

#pragma unroll
    for (int pr = 0; pr < PAIRS; ++pr) {
        int g0 = base + t + ((2 * pr)     << 9);
        int g1 = base + t + ((2 * pr + 1) << 9);
        float x0 = p[3 * g0 + 0], y0 = p[3 * g0 + 1], z0 = p[3 * g0 + 2];
        float x1 = p[3 * g1 + 0], y1 = p[3 * g1 + 1], z1 = p[3 * g1 + 2];
        CX[pr] = pack2(x0, x1);
        CY[pr] = pack2(y0, y1);
        CZ[pr] = pack2(z0, z1);
        d[2 * pr]     = INF;
        d[2 * pr + 1] = INF;
    }

    // First pick: cloud-local index 0. Every thread loads its coords (L1 broadcast).
    float sx = p[0], sy = p[1], sz = p[2];
    if (t == 0 && rank == 0) out[b * M_SAMP] = (float)(b * PTS);

    // Make sure both CTAs are alive before the per-iteration sync protocol.
    cluster.sync();

    for (int i = 1; i < M_SAMP; ++i) {
        const unsigned long long nx2 = pack2(-sx, -sx);
        const unsigned long long ny2 = pack2(-sy, -sy);
        const unsigned long long nz2 = pack2(-sz, -sz);

        float best = 0.0f;   // dists >= 0
        int jj = 0;

#pragma unroll
        for (int pr = 0; pr < PAIRS; ++pr) {
            // p - s as p + (-s): exact.
            unsigned long long dx = add2(CX[pr], nx2);
            unsigned long long dy = add2(CY[pr], ny2);
            unsigned long long dz = add2(CZ[pr], nz2);
            // (dx^2 + dy^2) + dz^2, all RN, no contraction (validated bit-exact).
            unsigned long long s  = add2(add2(mul2(dx, dx), mul2(dy, dy)), mul2(dz, dz));
            float lo, hi;
            unpack2(s, lo, hi);
            {
                float nd = fminf(d[2 * pr], lo);
                d[2 * pr] = nd;
                bool c = nd > best;
                best = c ? nd : best;
                jj   = c ? 2 * pr : jj;
            }
            {
                float nd = fminf(d[2 * pr + 1], hi);
                d[2 * pr + 1] = nd;
                bool c = nd > best;
                best = c ? nd : best;
                jj   = c ? 2 * pr + 1 : jj;
            }
        }

        // u64 key: high = dist bits (>=0, order-preserving), low = ~cloud_local_idx
        // so ties break toward the LOWEST index (jnp.argmax first-occurrence).
        const unsigned int gidx = (unsigned int)(base + t) + ((unsigned int)jj << 9);
        const unsigned long long mykey =
            ((unsigned long long)__float_as_uint(best) << 32) |
            (unsigned long long)(0xFFFFFFFFu - gidx);

        unsigned long long key = mykey;
#pragma unroll
        for (int off = 16; off > 0; off >>= 1) {
            unsigned long long o = __shfl_xor_sync(0xFFFFFFFFu, key, off);
            if (o > key) key = o;
        }
        if (lane == 0) skeys[wid] = key;
        __syncthreads();

        // CTA-local winner (all threads compute it; keys are unique per thread).
        unsigned long long kbest = skeys[0];
#pragma unroll
        for (int w = 1; w < 16; ++w) {
            unsigned long long o = skeys[w];
            if (o > kbest) kbest = o;
        }

        const int par = i & 1;

        // UNIQUE owner thread (its pre-reduction key equals the CTA max) publishes
        // {key, coords} to BOTH CTAs' exchange slots. Keys are unique per thread,
        // so exactly one thread in the CTA takes this branch.
        if (mykey == kbest) {
            const int jw  = jj;            // this thread's winning point
            const int prw = jw >> 1;
            const int hw  = jw & 1;
            float wx = 0.f, wy = 0.f, wz = 0.f;
#pragma unroll
            for (int pr = 0; pr < PAIRS; ++pr) {
                if (pr == prw) {
                    float l0, h0, l1, h1, l2, h2;
                    unpack2(CX[pr], l0, h0);
                    unpack2(CY[pr], l1, h1);
                    unpack2(CZ[pr], l2, h2);
                    wx = hw ? h0 : l0;
                    wy = hw ? h1 : l1;
                    wz = hw ? h2 : l2;
                }
            }
            // Local copy
            ekey[par][rank] = kbest;
            ecoord[par][rank][0] = wx;
            ecoord[par][rank][1] = wy;
            ecoord[par][rank][2] = wz;
            // Remote copy (peer CTA's same slot) via DSMEM
            unsigned peer = rank ^ 1u;
            unsigned long long* rk = cluster.map_shared_rank(&ekey[par][rank], peer);
            float* rc = cluster.map_shared_rank(&ecoord[par][rank][0], peer);
            *rk = kbest;
            rc[0] = wx; rc[1] = wy; rc[2] = wz;
        }

        // Cluster-wide barrier: release owner's writes, acquire peer's.
        // Also orders skeys reuse and exchange-slot reuse (double-buffered by parity).
        cluster.sync();

        const unsigned long long k0 = ekey[par][0];
        const unsigned long long k1 = ekey[par][1];
        const bool w1 = k1 > k0;                 // keys globally unique
        const unsigned long long gk = w1 ? k1 : k0;
        const unsigned int gw = 0xFFFFFFFFu - (unsigned int)gk;  // cloud-local winner

        sx = ecoord[par][w1 ? 1 : 0][0];
        sy = ecoord[par][w1 ? 1 : 0][1];
        sz = ecoord[par][w1 ? 1 : 0][2];

        if (t == 0 && rank == 0)
            out[b * M_SAMP + i] = (float)(b * PTS + (int)gw);
    }
}

extern "C" void kernel_launch(void* const* d_in, const int* in_sizes, int n_in,
                              void* d_out, int out_size)
{
    // Resolve pos BY SIZE (786432 floats), robust to input ordering.
    const float* pos = nullptr;
    for (int i = 0; i < n_in; ++i) {
        if (in_sizes[i] == N_CLOUDS * PTS * 3) { pos = (const float*)d_in[i]; break; }
    }
    if (!pos) pos = (const float*)d_in[0];

    float* out = (float*)d_out;   // [N_CLOUDS*M_SAMP] float32 index values

    fps_kernel<<<N_CLOUDS * 2, THREADS>>>(pos, out);
}